// round 11
// baseline (speedup 1.0000x reference)
#include <cuda_runtime.h>
#include <cuda_bf16.h>
#include <cstdint>

#define LATENT 128
#define MAXN 100352
#define TN 128            // nodes per tile

// ---------------- device globals (allocation-free scratch) ----------------
// Interleaved accumulator: per node 16 floats (64B):
//   [0..3] force.xyz,count  [4..7] torque.xyz,pad  [8..11] cons.xyz,pad  [12..15] pad
__device__ __align__(16) float g_acc[MAXN * 16];
__device__ float g_mlp[6 * MAXN];     // planar: [channel][node]
__device__ unsigned int g_ctr;
// W1 per MLP in mma B-fragment word layout: [0,8192) hi words, [8192,16384) lo words
__device__ __align__(16) uint32_t g_wb[4][16384];

// ---------------- helpers ----------------
__device__ __forceinline__ void mma16816(float* c, const uint32_t* a, uint32_t b0, uint32_t b1) {
    asm volatile(
        "mma.sync.aligned.m16n8k16.row.col.f32.bf16.bf16.f32 "
        "{%0,%1,%2,%3}, {%4,%5,%6,%7}, {%8,%9}, {%0,%1,%2,%3};"
        : "+f"(c[0]), "+f"(c[1]), "+f"(c[2]), "+f"(c[3])
        : "r"(a[0]), "r"(a[1]), "r"(a[2]), "r"(a[3]), "r"(b0), "r"(b1));
}

__device__ __forceinline__ void redv4(float* p, float a, float b, float c, float d) {
    asm volatile("red.global.add.v4.f32 [%0], {%1, %2, %3, %4};"
                 :: "l"(p), "f"(a), "f"(b), "f"(c), "f"(d) : "memory");
}

__device__ __forceinline__ void split_pack(float2 v, uint32_t& hw, uint32_t& lw) {
    __nv_bfloat16 h0 = __float2bfloat16(v.x);
    __nv_bfloat16 h1 = __float2bfloat16(v.y);
    __nv_bfloat16 l0 = __float2bfloat16(v.x - __bfloat162float(h0));
    __nv_bfloat16 l1 = __float2bfloat16(v.y - __bfloat162float(h1));
    __nv_bfloat162 hp; hp.x = h0; hp.y = h1;
    __nv_bfloat162 lp; lp.x = l0; lp.y = l1;
    hw = *(uint32_t*)&hp;
    lw = *(uint32_t*)&lp;
}

// ---------------- small kernels ----------------
__global__ void zero_kernel(int N) {
    int i = blockIdx.x * blockDim.x + threadIdx.x;
    if (i < N * 4) {
        ((float4*)g_acc)[i] = make_float4(0.f, 0.f, 0.f, 0.f);
    }
    if (i == 0) g_ctr = 0u;
}

struct PrepArgs { const float* W1[4]; };

// B-fragment layout: word idx r = ((nb*8+kb)*32 + lane)*2 + w
// lane: tig=lane&3, gid=lane>>2 ; k = kb*16 + tig*2 + w*8 ; n = nb*8 + gid
// word = bf16x2( W1[k][n], W1[k+1][n] )   (W1 row-major [k][n], 128x128)
__global__ void prep_w_kernel(PrepArgs a) {
    int idx = blockIdx.x * blockDim.x + threadIdx.x;   // 4 * 8192
    if (idx >= 4 * 8192) return;
    int m = idx >> 13;
    int r = idx & 8191;
    int w    = r & 1;
    int lane = (r >> 1) & 31;
    int kb   = (r >> 6) & 7;
    int nb   = r >> 9;
    int tig = lane & 3, gid = lane >> 2;
    int k = kb * 16 + tig * 2 + w * 8;
    int n = nb * 8 + gid;
    const float* W = a.W1[m];
    float2 v = make_float2(W[k * 128 + n], W[(k + 1) * 128 + n]);
    uint32_t hw, lw;
    split_pack(v, hw, lw);
    g_wb[m][r] = hw;
    g_wb[m][8192 + r] = lw;
}

// ---------------- fused kernel ----------------
struct FusedArgs {
    const float* latent;
    const float* b1[4];
    const float* W2[4];
    const float* b2[4];
    const int* recv;
    const float* ef;
    const float* et;
    const float* ec;
    int N, NB, E;
};

// smem: wbuf 65536 B | b1s 2048 B | w2s 3072 B | b2s 24 B
#define SM_B1   65536
#define SM_W2   67584
#define SM_B2   70656
#define SMEM_BYTES 70784

__device__ __constant__ int c_w2off[4] = {0, 128, 256, 640};
__device__ __constant__ int c_od[4]    = {1, 1, 3, 1};
__device__ __constant__ int c_oout[4]  = {0, 1, 2, 5};

__device__ __forceinline__ void edge_scalar_tail(const FusedArgs& a, int e) {
    int r = __ldg(&a.recv[e]);
    int e3 = 3 * e;
    float* p = &g_acc[16 * r];
    atomicAdd(p + 0, __ldg(&a.ef[e3 + 0]));
    atomicAdd(p + 1, __ldg(&a.ef[e3 + 1]));
    atomicAdd(p + 2, __ldg(&a.ef[e3 + 2]));
    atomicAdd(p + 3, 1.0f);
    atomicAdd(p + 4, __ldg(&a.et[e3 + 0]));
    atomicAdd(p + 5, __ldg(&a.et[e3 + 1]));
    atomicAdd(p + 6, __ldg(&a.et[e3 + 2]));
    atomicAdd(p + 8, __ldg(&a.ec[e3 + 0]));
    atomicAdd(p + 9, __ldg(&a.ec[e3 + 1]));
    atomicAdd(p + 10, __ldg(&a.ec[e3 + 2]));
}

__device__ __forceinline__ void edge1(int r, float fx, float fy, float fz,
                                      float tx, float ty, float tz,
                                      float cx, float cy, float cz) {
    float* p = &g_acc[16 * r];
    redv4(p + 0, fx, fy, fz, 1.0f);
    redv4(p + 4, tx, ty, tz, 0.0f);
    redv4(p + 8, cx, cy, cz, 0.0f);
}

__global__ __launch_bounds__(256, 2) void fused_kernel(FusedArgs args) {
    const int bid = blockIdx.x;
    const int tid = threadIdx.x;
    const bool is_node = ((bid % 3) == 0) && ((bid / 3) < args.NB);

    if (!is_node) {
        // ================= EDGE ROLE: block-level work stealing (R8 structure) =================
        const int E = args.E;
        const int C = E >> 2;
        const int tail = E & 3;
        if (bid == 1 && tid < tail) edge_scalar_tail(args, (C << 2) + tid);

        const int4* r4p = (const int4*)args.recv;
        const float4* f4 = (const float4*)args.ef;
        const float4* t4 = (const float4*)args.et;
        const float4* c4 = (const float4*)args.ec;
        __shared__ unsigned int s_base;
        for (;;) {
            __syncthreads();
            if (tid == 0) s_base = atomicAdd(&g_ctr, 256u);
            __syncthreads();
            unsigned int base = s_base;
            if (base >= (unsigned)C) break;
            unsigned int ch = base + tid;
            if (ch < (unsigned)C) {
                int4 r = __ldg(&r4p[ch]);
                float4 a0 = __ldg(&f4[3 * ch + 0]);
                float4 a1 = __ldg(&f4[3 * ch + 1]);
                float4 a2 = __ldg(&f4[3 * ch + 2]);
                float4 b0 = __ldg(&t4[3 * ch + 0]);
                float4 b1 = __ldg(&t4[3 * ch + 1]);
                float4 b2 = __ldg(&t4[3 * ch + 2]);
                float4 c0 = __ldg(&c4[3 * ch + 0]);
                float4 c1 = __ldg(&c4[3 * ch + 1]);
                float4 c2 = __ldg(&c4[3 * ch + 2]);
                edge1(r.x, a0.x, a0.y, a0.z, b0.x, b0.y, b0.z, c0.x, c0.y, c0.z);
                edge1(r.y, a0.w, a1.x, a1.y, b0.w, b1.x, b1.y, c0.w, c1.x, c1.y);
                edge1(r.z, a1.z, a1.w, a2.x, b1.z, b1.w, b2.x, c1.z, c1.w, c2.x);
                edge1(r.w, a2.y, a2.z, a2.w, b2.y, b2.z, b2.w, c2.y, c2.z, c2.w);
            }
        }
        return;
    }

    // ================= NODE ROLE: mma.sync bf16-split MLPs =================
    extern __shared__ char smem[];
    uint32_t* wbuf = (uint32_t*)smem;
    float* b1s = (float*)(smem + SM_B1);
    float* w2s = (float*)(smem + SM_W2);
    float* b2s = (float*)(smem + SM_B2);

    const int wid = tid >> 5;
    const int lane = tid & 31;
    const int tig = lane & 3;     // thread-in-group (k pairs / cols)
    const int gid = lane >> 2;    // group id (rows / n)
    const int tile = bid / 3;
    const int base = tile * TN;
    const int N = args.N;

    // small tables
    for (int i = tid; i < 512; i += 256) b1s[i] = args.b1[i >> 7][i & 127];
    for (int i = tid; i < 768; i += 256) {
        int m, o;
        if (i < 128)      { m = 0; o = i; }
        else if (i < 256) { m = 1; o = i - 128; }
        else if (i < 640) { m = 2; o = i - 256; }
        else              { m = 3; o = i - 640; }
        w2s[i] = args.W2[m][o];
    }
    if (tid < 6) {
        int m = (tid == 0) ? 0 : (tid == 1) ? 1 : (tid < 5) ? 2 : 3;
        int o = (tid >= 2 && tid < 5) ? tid - 2 : 0;
        b2s[tid] = args.b2[m][o];
    }

    // ---- build A fragments (hi/lo) from global X; warp owns rows [wid*16, wid*16+16) ----
    const int gn0 = base + wid * 16 + gid;      // rows gid and gid+8
    const int gn1 = gn0 + 8;
    const bool v0 = gn0 < N, v1 = gn1 < N;
    const float* x0 = args.latent + (size_t)gn0 * LATENT;
    const float* x1 = args.latent + (size_t)gn1 * LATENT;

    uint32_t ah[32], al[32];
    #pragma unroll
    for (int kb = 0; kb < 8; kb++) {
        const int kc = kb * 16 + tig * 2;
        float2 p00 = v0 ? *(const float2*)(x0 + kc)     : make_float2(0.f, 0.f);
        float2 p01 = v0 ? *(const float2*)(x0 + kc + 8) : make_float2(0.f, 0.f);
        float2 p10 = v1 ? *(const float2*)(x1 + kc)     : make_float2(0.f, 0.f);
        float2 p11 = v1 ? *(const float2*)(x1 + kc + 8) : make_float2(0.f, 0.f);
        split_pack(p00, ah[kb * 4 + 0], al[kb * 4 + 0]);
        split_pack(p10, ah[kb * 4 + 1], al[kb * 4 + 1]);
        split_pack(p01, ah[kb * 4 + 2], al[kb * 4 + 2]);
        split_pack(p11, ah[kb * 4 + 3], al[kb * 4 + 3]);
    }

    for (int m = 0; m < 4; m++) {
        __syncthreads();   // previous iteration's wbuf reads done
        {
            const uint4* src = (const uint4*)&g_wb[m][0];
            uint4* dst = (uint4*)wbuf;
            #pragma unroll 1
            for (int i = tid; i < 4096; i += 1024) {
                uint4 t0 = __ldg(&src[i]);
                uint4 t1 = __ldg(&src[i + 256]);
                uint4 t2 = __ldg(&src[i + 512]);
                uint4 t3 = __ldg(&src[i + 768]);
                dst[i] = t0;
                dst[i + 256] = t1;
                dst[i + 512] = t2;
                dst[i + 768] = t3;
            }
        }
        __syncthreads();   // weights ready

        const int od = c_od[m];
        const int w2o = c_w2off[m];
        const int oo = c_oout[m];
        const float* b1m = b1s + m * 128;
        float pr0[3] = {0.f, 0.f, 0.f};
        float pr1[3] = {0.f, 0.f, 0.f};

        #pragma unroll 2
        for (int nb = 0; nb < 16; nb++) {
            float acc[4] = {0.f, 0.f, 0.f, 0.f};
            #pragma unroll
            for (int kb = 0; kb < 8; kb++) {
                const int wi = (nb * 8 + kb) * 64 + lane * 2;
                uint2 bh = *(const uint2*)&wbuf[wi];
                uint2 bl = *(const uint2*)&wbuf[8192 + wi];
                mma16816(acc, &ah[kb * 4], bh.x, bh.y);
                mma16816(acc, &al[kb * 4], bh.x, bh.y);
                mma16816(acc, &ah[kb * 4], bl.x, bl.y);
            }
            const int col0 = nb * 8 + tig * 2;
            const int col1 = col0 + 1;
            float h0 = fmaxf(acc[0] + b1m[col0], 0.f);
            float h1 = fmaxf(acc[1] + b1m[col1], 0.f);
            float h2 = fmaxf(acc[2] + b1m[col0], 0.f);
            float h3 = fmaxf(acc[3] + b1m[col1], 0.f);
            if (od == 1) {
                pr0[0] += h0 * w2s[w2o + col0] + h1 * w2s[w2o + col1];
                pr1[0] += h2 * w2s[w2o + col0] + h3 * w2s[w2o + col1];
            } else {
                #pragma unroll
                for (int o = 0; o < 3; o++) {
                    pr0[o] += h0 * w2s[w2o + col0 * 3 + o] + h1 * w2s[w2o + col1 * 3 + o];
                    pr1[o] += h2 * w2s[w2o + col0 * 3 + o] + h3 * w2s[w2o + col1 * 3 + o];
                }
            }
        }

        // reduce across the 4 lanes of each row group (tig bits 0,1)
        #pragma unroll
        for (int o = 0; o < 3; o++) {
            pr0[o] += __shfl_xor_sync(0xffffffffu, pr0[o], 1);
            pr0[o] += __shfl_xor_sync(0xffffffffu, pr0[o], 2);
            pr1[o] += __shfl_xor_sync(0xffffffffu, pr1[o], 1);
            pr1[o] += __shfl_xor_sync(0xffffffffu, pr1[o], 2);
        }
        if (tig == 0) {
            if (v0) {
                g_mlp[oo * MAXN + gn0] = pr0[0] + b2s[oo];
                if (od == 3) {
                    g_mlp[3 * MAXN + gn0] = pr0[1] + b2s[3];
                    g_mlp[4 * MAXN + gn0] = pr0[2] + b2s[4];
                }
            }
            if (v1) {
                g_mlp[oo * MAXN + gn1] = pr1[0] + b2s[oo];
                if (od == 3) {
                    g_mlp[3 * MAXN + gn1] = pr1[1] + b2s[3];
                    g_mlp[4 * MAXN + gn1] = pr1[2] + b2s[4];
                }
            }
        }
    }
}

// ---------------- combine ----------------
__global__ __launch_bounds__(256) void combine_kernel(const float* __restrict__ vel,
                                                      float* __restrict__ out, int N) {
    int n = blockIdx.x * blockDim.x + threadIdx.x;
    if (n >= N) return;
    const float4* acc = (const float4*)&g_acc[n * 16];
    float4 F = acc[0];
    float4 T = acc[1];
    float4 Cc = acc[2];
    float im = g_mlp[0 * MAXN + n];
    float ii = g_mlp[1 * MAXN + n];
    float ex = g_mlp[2 * MAXN + n];
    float ey = g_mlp[3 * MAXN + n];
    float ez = g_mlp[4 * MAXN + n];
    float vs = g_mlp[5 * MAXN + n];
    float cnt = fmaxf(F.w, 1.0f);
    int b = n * 3;
    int N3 = N * 3;
    out[b + 0] = im * F.x;
    out[b + 1] = im * F.y;
    out[b + 2] = im * F.z;
    out[N3 + b + 0] = ii * T.x;
    out[N3 + b + 1] = ii * T.y;
    out[N3 + b + 2] = ii * T.z;
    out[2 * N3 + b + 0] = (vel[b + 0] + ex) * vs + Cc.x / cnt;
    out[2 * N3 + b + 1] = (vel[b + 1] + ey) * vs + Cc.y / cnt;
    out[2 * N3 + b + 2] = (vel[b + 2] + ez) * vs + Cc.z / cnt;
}

extern "C" void kernel_launch(void* const* d_in, const int* in_sizes, int n_in,
                              void* d_out, int out_size) {
    const int* ei       = (const int*)d_in[0];
    const float* latent = (const float*)d_in[1];
    const float* vel    = (const float*)d_in[2];
    const float* ef     = (const float*)d_in[3];
    const float* et     = (const float*)d_in[4];
    const float* ec     = (const float*)d_in[5];

    const int E = in_sizes[0] / 2;
    const int N = in_sizes[1] / LATENT;

    PrepArgs pa;
    FusedArgs fa;
    fa.latent = latent;
    for (int m = 0; m < 4; m++) {
        pa.W1[m] = (const float*)d_in[6 + 4 * m + 0];
        fa.b1[m] = (const float*)d_in[6 + 4 * m + 1];
        fa.W2[m] = (const float*)d_in[6 + 4 * m + 2];
        fa.b2[m] = (const float*)d_in[6 + 4 * m + 3];
    }
    fa.recv = ei + E;
    fa.ef = ef;
    fa.et = et;
    fa.ec = ec;
    fa.N = N;
    fa.E = E;
    const int NB = (N + TN - 1) / TN;
    fa.NB = NB;

    (void)cudaFuncSetAttribute(fused_kernel,
                               cudaFuncAttributeMaxDynamicSharedMemorySize,
                               SMEM_BYTES);

    zero_kernel<<<(N * 4 + 255) / 256, 256>>>(N);
    prep_w_kernel<<<(4 * 8192 + 255) / 256, 256>>>(pa);
    fused_kernel<<<NB * 3, 256, SMEM_BYTES>>>(fa);
    combine_kernel<<<(N + 255) / 256, 256>>>(vel, (float*)d_out, N);
}